// round 14
// baseline (speedup 1.0000x reference)
#include <cuda_runtime.h>
#include <cuda_bf16.h>
#include <cstdint>

// out[t][o] = sum_h R[t][h] * W[o][h],  R = x @ basis^T, W = amp*cos(phase)
// Step 2 (R): mma.m16n8k8 TF32 (R9 register-prefetch version).
// Step 3 (out): mma.m16n8k8 TF32; epilogue STS -> CTA stage -> 512B TMA bulk
//               stores (async proxy reads smem: no L1 LDS/STG wavefronts).
#define TOKENS 16384
#define INF    1024
#define HARM   32
#define OUTF   4096

__device__ __align__(16) float g_R[TOKENS * HARM];   // 2 MB
__device__ __align__(16) float g_W[OUTF * HARM];     // 512 KB

__device__ __forceinline__ uint32_t smem_u32(const void* p) {
    uint32_t a;
    asm("{ .reg .u64 t; cvta.to.shared.u64 t, %1; cvt.u32.u64 %0, t; }"
        : "=r"(a) : "l"(p));
    return a;
}
__device__ __forceinline__ float tf32_rna(float v) {
    float r;
    asm("cvt.rna.tf32.f32 %0, %1;" : "=f"(r) : "f"(v));
    return r;
}
__device__ __forceinline__ uint32_t tf32_r(uint32_t v) {
    uint32_t r;
    asm("cvt.rna.tf32.f32 %0, %1;" : "=r"(r) : "r"(v));
    return r;
}

// ---------------------------------------------------------------------------
// Step 2 (+W prep): CTAs [0,256) R = x @ basis^T TF32 mma, register prefetch
// (R9-proven). CTAs [256,288): W = tf32(amp*cos(phase)).
// ---------------------------------------------------------------------------
#define XPITCH 68
__global__ __launch_bounds__(128) void resonance_tf32_kernel(
    const float* __restrict__ x, const float* __restrict__ basis,
    const float* __restrict__ phase, const float* __restrict__ amp) {
    if (blockIdx.x >= 256) {
        int base = (blockIdx.x - 256) * 4096;
#pragma unroll
        for (int r = 0; r < 32; r++) {
            int idx = base + threadIdx.x + r * 128;
            g_W[idx] = tf32_rna(amp[idx] * cosf(phase[idx]));
        }
        return;
    }

    __shared__ float sx[64 * XPITCH];
    __shared__ float sb[32 * XPITCH];

    int tid  = threadIdx.x;
    int lane = tid & 31;
    int wid  = tid >> 5;
    int tb   = blockIdx.x * 64;

    uint32_t sx_b = smem_u32(sx), sb_b = smem_u32(sb);

    float acc[4][4];
#pragma unroll
    for (int j = 0; j < 4; j++)
#pragma unroll
        for (int c = 0; c < 4; c++) acc[j][c] = 0.0f;

    const float4* gx = reinterpret_cast<const float4*>(x);
    const float4* gb = reinterpret_cast<const float4*>(basis);

    float4 xp[8], bp[4];
#pragma unroll
    for (int r = 0; r < 8; r++) {
        int q = tid + r * 128;
        int row = q >> 4, c4 = q & 15;
        xp[r] = gx[(long)(tb + row) * (INF / 4) + c4];
    }
#pragma unroll
    for (int r = 0; r < 4; r++) {
        int q = tid + r * 128;
        int row = q >> 4, c4 = q & 15;
        bp[r] = gb[row * (INF / 4) + c4];
    }

    for (int ck = 0; ck < 16; ck++) {
        if (ck > 0) __syncthreads();
#pragma unroll
        for (int r = 0; r < 8; r++) {
            int q = tid + r * 128;
            int row = q >> 4, c4 = q & 15;
            *reinterpret_cast<float4*>(&sx[row * XPITCH + c4 * 4]) = xp[r];
        }
#pragma unroll
        for (int r = 0; r < 4; r++) {
            int q = tid + r * 128;
            int row = q >> 4, c4 = q & 15;
            *reinterpret_cast<float4*>(&sb[row * XPITCH + c4 * 4]) = bp[r];
        }
        __syncthreads();

        if (ck < 15) {
            int kc4 = (ck + 1) * 16;
#pragma unroll
            for (int r = 0; r < 8; r++) {
                int q = tid + r * 128;
                int row = q >> 4, c4 = q & 15;
                xp[r] = gx[(long)(tb + row) * (INF / 4) + kc4 + c4];
            }
#pragma unroll
            for (int r = 0; r < 4; r++) {
                int q = tid + r * 128;
                int row = q >> 4, c4 = q & 15;
                bp[r] = gb[row * (INF / 4) + kc4 + c4];
            }
        }

#pragma unroll
        for (int ks = 0; ks < 8; ks++) {
            uint32_t af[4];
            {
                int row = wid * 16 + (lane & 15);
                uint32_t ao = sx_b + (uint32_t)row * (XPITCH * 4) + ks * 32 + (lane >> 4) * 16;
                asm volatile(
                    "ldmatrix.sync.aligned.m8n8.x4.shared.b16 {%0,%1,%2,%3}, [%4];"
                    : "=r"(af[0]), "=r"(af[1]), "=r"(af[2]), "=r"(af[3])
                    : "r"(ao));
#pragma unroll
                for (int c = 0; c < 4; c++) af[c] = tf32_r(af[c]);
            }
#pragma unroll
            for (int j = 0; j < 4; j++) {
                int nrow = j * 8 + (lane & 7);
                uint32_t bo = sb_b + (uint32_t)nrow * (XPITCH * 4) + ks * 32 + ((lane >> 3) & 1) * 16;
                uint32_t bf[2];
                asm volatile(
                    "ldmatrix.sync.aligned.m8n8.x2.shared.b16 {%0,%1}, [%2];"
                    : "=r"(bf[0]), "=r"(bf[1]) : "r"(bo));
                bf[0] = tf32_r(bf[0]);
                bf[1] = tf32_r(bf[1]);
                asm volatile(
                    "mma.sync.aligned.m16n8k8.row.col.f32.tf32.tf32.f32 "
                    "{%0,%1,%2,%3}, {%4,%5,%6,%7}, {%8,%9}, {%0,%1,%2,%3};"
                    : "+f"(acc[j][0]), "+f"(acc[j][1]), "+f"(acc[j][2]), "+f"(acc[j][3])
                    : "r"(af[0]), "r"(af[1]), "r"(af[2]), "r"(af[3]),
                      "r"(bf[0]), "r"(bf[1]));
            }
        }
    }

    int qrow = lane >> 2;
    int qcol = (lane & 3) * 2;
#pragma unroll
    for (int j = 0; j < 4; j++) {
#pragma unroll
        for (int hh = 0; hh < 2; hh++) {
            long t = tb + wid * 16 + qrow + hh * 8;
            float v0 = tf32_rna(acc[j][hh * 2 + 0]);
            float v1 = tf32_rna(acc[j][hh * 2 + 1]);
            *reinterpret_cast<float2*>(&g_R[t * HARM + j * 8 + qcol]) =
                make_float2(v0, v1);
        }
    }
}

// ---------------------------------------------------------------------------
// Step 3: out = R @ W^T via mma.m16n8k8 TF32, K=32 single term.
// CTA 128 tokens x 256 outputs (2 B-subtiles up-front). 8 warps 2(m)x4(n).
// Epilogue per (nb,i): all warps STS a 32x128 slab into a CTA stage
// (pitch 132), then warp 0 issues 32 x 512B cp.async.bulk S2G.
// Double-buffered; buffer reuse gated by wait_group.read.
// ---------------------------------------------------------------------------
#define TPITCH 36
#define TILE_BYTES (128 * TPITCH * 4)        // 18432
#define STAGE_OFF  (3 * TILE_BYTES)          // 55296
#define SPITCH 132                            // stage pitch (words)
#define SLAB_BYTES (32 * SPITCH * 4)         // 16896
#define SM3_TOTAL (STAGE_OFF + 2 * SLAB_BYTES)   // 89088
#define NBT 2

__global__ __launch_bounds__(256, 2) void holo_tf32_kernel(float* __restrict__ out) {
    extern __shared__ char smem[];
    char* sA = smem;
    float* stage = reinterpret_cast<float*>(smem + STAGE_OFF);

    int tid  = threadIdx.x;
    int lane = tid & 31;
    int wid  = tid >> 5;
    int warp_m = wid >> 2;   // 0..1
    int warp_n = wid & 3;    // 0..3

    int ob0 = blockIdx.x * 256;
    int tb  = blockIdx.y * 128;

    const float4* gA = reinterpret_cast<const float4*>(&g_R[(long)tb * HARM]);
    const float4* gB = reinterpret_cast<const float4*>(&g_W[(long)ob0 * HARM]);

#pragma unroll
    for (int r = 0; r < 4; r++) {
        int q = tid + r * 256;        // 0..1023
        int row = q >> 3, ch = q & 7;
        uint32_t soff = (uint32_t)row * (TPITCH * 4) + ch * 16;
        *reinterpret_cast<float4*>(sA + soff) = gA[q];
        *reinterpret_cast<float4*>(sA + TILE_BYTES + soff) = gB[q];
        *reinterpret_cast<float4*>(sA + 2 * TILE_BYTES + soff) = gB[1024 + q];
    }
    __syncthreads();

    uint32_t sAb = smem_u32(sA);
    int qrow = lane >> 2;
    int qcol = (lane & 3) * 2;
    int ep = 0;

#pragma unroll
    for (int nb = 0; nb < NBT; nb++) {
        uint32_t sBb = sAb + TILE_BYTES + (uint32_t)nb * TILE_BYTES;

        float acc[4][4][4];
#pragma unroll
        for (int i = 0; i < 4; i++)
#pragma unroll
            for (int j = 0; j < 4; j++)
#pragma unroll
                for (int c = 0; c < 4; c++) acc[i][j][c] = 0.0f;

#pragma unroll
        for (int ks = 0; ks < 4; ks++) {
            uint32_t af[4][4];
#pragma unroll
            for (int i = 0; i < 4; i++) {
                int row = warp_m * 64 + i * 16 + (lane & 15);
                uint32_t addr = sAb + (uint32_t)row * (TPITCH * 4) + ks * 32 + (lane >> 4) * 16;
                asm volatile(
                    "ldmatrix.sync.aligned.m8n8.x4.shared.b16 {%0,%1,%2,%3}, [%4];"
                    : "=r"(af[i][0]), "=r"(af[i][1]), "=r"(af[i][2]), "=r"(af[i][3])
                    : "r"(addr));
            }
            uint32_t bf[4][2];
#pragma unroll
            for (int j = 0; j < 4; j++) {
                int orow = warp_n * 32 + j * 8 + (lane & 7);
                uint32_t addr = sBb + (uint32_t)orow * (TPITCH * 4) + ks * 32 + ((lane >> 3) & 1) * 16;
                asm volatile(
                    "ldmatrix.sync.aligned.m8n8.x2.shared.b16 {%0,%1}, [%2];"
                    : "=r"(bf[j][0]), "=r"(bf[j][1])
                    : "r"(addr));
            }
#pragma unroll
            for (int i = 0; i < 4; i++)
#pragma unroll
                for (int j = 0; j < 4; j++) {
                    asm volatile(
                        "mma.sync.aligned.m16n8k8.row.col.f32.tf32.tf32.f32 "
                        "{%0,%1,%2,%3}, {%4,%5,%6,%7}, {%8,%9}, {%0,%1,%2,%3};"
                        : "+f"(acc[i][j][0]), "+f"(acc[i][j][1]),
                          "+f"(acc[i][j][2]), "+f"(acc[i][j][3])
                        : "r"(af[i][0]), "r"(af[i][1]), "r"(af[i][2]), "r"(af[i][3]),
                          "r"(bf[j][0]), "r"(bf[j][1]));
                }
        }

        // Epilogue: per i-slab, CTA-staged 32x128 -> 512B TMA bulk per row.
#pragma unroll
        for (int i = 0; i < 4; i++) {
            float* buf = stage + (ep & 1) * (32 * SPITCH);
            if (ep >= 2) {
                // buffer (ep-2) must be read-drained before overwrite
                if (wid == 0)
                    asm volatile("cp.async.bulk.wait_group.read 1;" ::: "memory");
                __syncthreads();
            }
            // STS: warp writes its 16x32 fragment block into the slab.
            int srow0 = warp_m * 16;
            int scol0 = warp_n * 32;
#pragma unroll
            for (int j = 0; j < 4; j++) {
                *reinterpret_cast<float2*>(
                    &buf[(srow0 + qrow) * SPITCH + scol0 + j * 8 + qcol]) =
                    make_float2(acc[i][j][0], acc[i][j][1]);
                *reinterpret_cast<float2*>(
                    &buf[(srow0 + qrow + 8) * SPITCH + scol0 + j * 8 + qcol]) =
                    make_float2(acc[i][j][2], acc[i][j][3]);
            }
            asm volatile("fence.proxy.async.shared::cta;" ::: "memory");
            __syncthreads();
            if (wid == 0) {
                // lane -> one slab row: wm = lane>>4, lr = lane&15
                int wm = lane >> 4, lr = lane & 15;
                long grow = tb + wm * 64 + i * 16 + lr;
                long gcol = ob0 + nb * 128;
                uint32_t sa = smem_u32(&buf[(wm * 16 + lr) * SPITCH]);
                asm volatile(
                    "cp.async.bulk.global.shared::cta.bulk_group [%0], [%1], 512;"
                    :: "l"(&out[grow * OUTF + gcol]), "r"(sa) : "memory");
                asm volatile("cp.async.bulk.commit_group;" ::: "memory");
            }
            ep++;
        }
    }

    // Drain all pending bulk stores (smem must stay valid until reads done).
    if (wid == 0)
        asm volatile("cp.async.bulk.wait_group 0;" ::: "memory");
    __syncthreads();
}

// ---------------------------------------------------------------------------
extern "C" void kernel_launch(void* const* d_in, const int* in_sizes, int n_in,
                              void* d_out, int out_size) {
    const float* x     = (const float*)d_in[0];  // [16384,1024]
    const float* basis = (const float*)d_in[1];  // [32,1024]
    const float* phase = (const float*)d_in[2];  // [4096,32]
    const float* amp   = (const float*)d_in[3];  // [4096,32]
    float* out = (float*)d_out;                  // [16384,4096]

    cudaFuncSetAttribute(holo_tf32_kernel,
                         cudaFuncAttributeMaxDynamicSharedMemorySize, SM3_TOTAL);

    resonance_tf32_kernel<<<256 + 32, 128>>>(x, basis, phase, amp);
    dim3 gridC(OUTF / 256, TOKENS / 128);
    holo_tf32_kernel<<<gridC, 256, SM3_TOTAL>>>(out);
}

// round 15
// speedup vs baseline: 1.3726x; 1.3726x over previous
#include <cuda_runtime.h>
#include <cuda_bf16.h>
#include <cstdint>

// out[t][o] = sum_h R[t][h] * W[o][h],  R = x @ basis^T, W = amp*cos(phase)
// Step 2 (R): mma.m16n8k8 TF32, 32-token CTAs (2x thread count -> 2x MLP).
// Step 3 (out): mma.m16n8k8 TF32, R9-proven staged epilogue (52.9us).
#define TOKENS 16384
#define INF    1024
#define HARM   32
#define OUTF   4096

__device__ __align__(16) float g_R[TOKENS * HARM];   // 2 MB
__device__ __align__(16) float g_W[OUTF * HARM];     // 512 KB

__device__ __forceinline__ uint32_t smem_u32(const void* p) {
    uint32_t a;
    asm("{ .reg .u64 t; cvta.to.shared.u64 t, %1; cvt.u32.u64 %0, t; }"
        : "=r"(a) : "l"(p));
    return a;
}
__device__ __forceinline__ float tf32_rna(float v) {
    float r;
    asm("cvt.rna.tf32.f32 %0, %1;" : "=f"(r) : "f"(v));
    return r;
}
__device__ __forceinline__ uint32_t tf32_r(uint32_t v) {
    uint32_t r;
    asm("cvt.rna.tf32.f32 %0, %1;" : "=r"(r) : "r"(v));
    return r;
}

// ---------------------------------------------------------------------------
// Step 2 (+W prep): CTAs [0,512) compute R = x @ basis^T via TF32 mma.
// Tile 32 tokens x 32 harmonics, 128 threads (4 warps = 2m x 2n).
// K chunks of 64, register prefetch. CTAs [512,544): W = tf32(amp*cos(phase)).
// ---------------------------------------------------------------------------
#define XPITCH 68
__global__ __launch_bounds__(128) void resonance_tf32_kernel(
    const float* __restrict__ x, const float* __restrict__ basis,
    const float* __restrict__ phase, const float* __restrict__ amp) {
    if (blockIdx.x >= 512) {
        int base = (blockIdx.x - 512) * 4096;
#pragma unroll
        for (int r = 0; r < 32; r++) {
            int idx = base + threadIdx.x + r * 128;
            g_W[idx] = tf32_rna(amp[idx] * cosf(phase[idx]));
        }
        return;
    }

    __shared__ float sx[32 * XPITCH];   // 8.7 KB
    __shared__ float sb[32 * XPITCH];   // 8.7 KB

    int tid  = threadIdx.x;
    int lane = tid & 31;
    int wid  = tid >> 5;
    int warp_m = wid >> 1;   // 0..1 -> 16-row mtile
    int warp_n = wid & 1;    // 0..1 -> 16-col ntile (2 j-subtiles of 8)
    int tb   = blockIdx.x * 32;

    uint32_t sx_b = smem_u32(sx), sb_b = smem_u32(sb);

    float acc[2][4];
#pragma unroll
    for (int j = 0; j < 2; j++)
#pragma unroll
        for (int c = 0; c < 4; c++) acc[j][c] = 0.0f;

    const float4* gx = reinterpret_cast<const float4*>(x);
    const float4* gb = reinterpret_cast<const float4*>(basis);

    float4 xp[4], bp[4];
    // prefetch chunk 0: x 32x64 (512 f4, 4/thread), basis 32x64 (4/thread)
#pragma unroll
    for (int r = 0; r < 4; r++) {
        int q = tid + r * 128;
        int row = q >> 4, c4 = q & 15;
        xp[r] = gx[(long)(tb + row) * (INF / 4) + c4];
        bp[r] = gb[row * (INF / 4) + c4];
    }

    for (int ck = 0; ck < 16; ck++) {
        if (ck > 0) __syncthreads();
#pragma unroll
        for (int r = 0; r < 4; r++) {
            int q = tid + r * 128;
            int row = q >> 4, c4 = q & 15;
            *reinterpret_cast<float4*>(&sx[row * XPITCH + c4 * 4]) = xp[r];
            *reinterpret_cast<float4*>(&sb[row * XPITCH + c4 * 4]) = bp[r];
        }
        __syncthreads();

        if (ck < 15) {
            int kc4 = (ck + 1) * 16;
#pragma unroll
            for (int r = 0; r < 4; r++) {
                int q = tid + r * 128;
                int row = q >> 4, c4 = q & 15;
                xp[r] = gx[(long)(tb + row) * (INF / 4) + kc4 + c4];
                bp[r] = gb[row * (INF / 4) + kc4 + c4];
            }
        }

#pragma unroll
        for (int ks = 0; ks < 8; ks++) {
            uint32_t af[4];
            {
                int row = warp_m * 16 + (lane & 15);
                uint32_t ao = sx_b + (uint32_t)row * (XPITCH * 4) + ks * 32 + (lane >> 4) * 16;
                asm volatile(
                    "ldmatrix.sync.aligned.m8n8.x4.shared.b16 {%0,%1,%2,%3}, [%4];"
                    : "=r"(af[0]), "=r"(af[1]), "=r"(af[2]), "=r"(af[3])
                    : "r"(ao));
#pragma unroll
                for (int c = 0; c < 4; c++) af[c] = tf32_r(af[c]);
            }
#pragma unroll
            for (int j = 0; j < 2; j++) {
                int nrow = warp_n * 16 + j * 8 + (lane & 7);
                uint32_t bo = sb_b + (uint32_t)nrow * (XPITCH * 4) + ks * 32 + ((lane >> 3) & 1) * 16;
                uint32_t bf[2];
                asm volatile(
                    "ldmatrix.sync.aligned.m8n8.x2.shared.b16 {%0,%1}, [%2];"
                    : "=r"(bf[0]), "=r"(bf[1]) : "r"(bo));
                bf[0] = tf32_r(bf[0]);
                bf[1] = tf32_r(bf[1]);
                asm volatile(
                    "mma.sync.aligned.m16n8k8.row.col.f32.tf32.tf32.f32 "
                    "{%0,%1,%2,%3}, {%4,%5,%6,%7}, {%8,%9}, {%0,%1,%2,%3};"
                    : "+f"(acc[j][0]), "+f"(acc[j][1]), "+f"(acc[j][2]), "+f"(acc[j][3])
                    : "r"(af[0]), "r"(af[1]), "r"(af[2]), "r"(af[3]),
                      "r"(bf[0]), "r"(bf[1]));
            }
        }
    }

    // Epilogue: tf32-rounded fp32 R, coalesced float2 stores.
    int qrow = lane >> 2;
    int qcol = (lane & 3) * 2;
#pragma unroll
    for (int j = 0; j < 2; j++) {
#pragma unroll
        for (int hh = 0; hh < 2; hh++) {
            long t = tb + warp_m * 16 + qrow + hh * 8;
            float v0 = tf32_rna(acc[j][hh * 2 + 0]);
            float v1 = tf32_rna(acc[j][hh * 2 + 1]);
            *reinterpret_cast<float2*>(
                &g_R[t * HARM + warp_n * 16 + j * 8 + qcol]) =
                make_float2(v0, v1);
        }
    }
}

// ---------------------------------------------------------------------------
// Step 3: out = R @ W^T via mma.m16n8k8 TF32, K=32 single term.
// CTA 128 tokens x 256 outputs (2 B-subtiles up-front). 8 warps 2(m)x4(n).
// Tiles pitch 36 f32. Staged epilogue -> __stcs STG.128.
// (R9 version verbatim — measured 52.9us)
// ---------------------------------------------------------------------------
#define TPITCH 36
#define TILE_BYTES (128 * TPITCH * 4)       // 18432
#define SM3_TOTAL (3 * TILE_BYTES)          // 55296
#define WSTRIDE 40
#define NBT 2

__global__ __launch_bounds__(256, 2) void holo_tf32_kernel(float* __restrict__ out) {
    extern __shared__ char smem[];
    __shared__ float wstage[8][16 * WSTRIDE];
    char* sA = smem;

    int tid  = threadIdx.x;
    int lane = tid & 31;
    int wid  = tid >> 5;
    int warp_m = wid >> 2;   // 0..1
    int warp_n = wid & 3;    // 0..3

    int ob0 = blockIdx.x * 256;
    int tb  = blockIdx.y * 128;

    const float4* gA = reinterpret_cast<const float4*>(&g_R[(long)tb * HARM]);
    const float4* gB = reinterpret_cast<const float4*>(&g_W[(long)ob0 * HARM]);

#pragma unroll
    for (int r = 0; r < 4; r++) {
        int q = tid + r * 256;        // 0..1023
        int row = q >> 3, ch = q & 7;
        uint32_t soff = (uint32_t)row * (TPITCH * 4) + ch * 16;
        *reinterpret_cast<float4*>(sA + soff) = gA[q];
        *reinterpret_cast<float4*>(sA + TILE_BYTES + soff) = gB[q];
        *reinterpret_cast<float4*>(sA + 2 * TILE_BYTES + soff) = gB[1024 + q];
    }
    __syncthreads();

    uint32_t sAb = smem_u32(sA);
    int qrow = lane >> 2;
    int qcol = (lane & 3) * 2;

#pragma unroll
    for (int nb = 0; nb < NBT; nb++) {
        uint32_t sBb = sAb + TILE_BYTES + (uint32_t)nb * TILE_BYTES;

        float acc[4][4][4];
#pragma unroll
        for (int i = 0; i < 4; i++)
#pragma unroll
            for (int j = 0; j < 4; j++)
#pragma unroll
                for (int c = 0; c < 4; c++) acc[i][j][c] = 0.0f;

#pragma unroll
        for (int ks = 0; ks < 4; ks++) {
            uint32_t af[4][4];
#pragma unroll
            for (int i = 0; i < 4; i++) {
                int row = warp_m * 64 + i * 16 + (lane & 15);
                uint32_t addr = sAb + (uint32_t)row * (TPITCH * 4) + ks * 32 + (lane >> 4) * 16;
                asm volatile(
                    "ldmatrix.sync.aligned.m8n8.x4.shared.b16 {%0,%1,%2,%3}, [%4];"
                    : "=r"(af[i][0]), "=r"(af[i][1]), "=r"(af[i][2]), "=r"(af[i][3])
                    : "r"(addr));
            }
            uint32_t bf[4][2];
#pragma unroll
            for (int j = 0; j < 4; j++) {
                int orow = warp_n * 32 + j * 8 + (lane & 7);
                uint32_t addr = sBb + (uint32_t)orow * (TPITCH * 4) + ks * 32 + ((lane >> 3) & 1) * 16;
                asm volatile(
                    "ldmatrix.sync.aligned.m8n8.x2.shared.b16 {%0,%1}, [%2];"
                    : "=r"(bf[j][0]), "=r"(bf[j][1])
                    : "r"(addr));
            }
#pragma unroll
            for (int i = 0; i < 4; i++)
#pragma unroll
                for (int j = 0; j < 4; j++) {
                    asm volatile(
                        "mma.sync.aligned.m16n8k8.row.col.f32.tf32.tf32.f32 "
                        "{%0,%1,%2,%3}, {%4,%5,%6,%7}, {%8,%9}, {%0,%1,%2,%3};"
                        : "+f"(acc[i][j][0]), "+f"(acc[i][j][1]),
                          "+f"(acc[i][j][2]), "+f"(acc[i][j][3])
                        : "r"(af[i][0]), "r"(af[i][1]), "r"(af[i][2]), "r"(af[i][3]),
                          "r"(bf[j][0]), "r"(bf[j][1]));
                }
        }

        float* wb = wstage[wid];
#pragma unroll
        for (int i = 0; i < 4; i++) {
#pragma unroll
            for (int j = 0; j < 4; j++) {
                *reinterpret_cast<float2*>(&wb[qrow * WSTRIDE + j * 8 + qcol]) =
                    make_float2(acc[i][j][0], acc[i][j][1]);
                *reinterpret_cast<float2*>(&wb[(qrow + 8) * WSTRIDE + j * 8 + qcol]) =
                    make_float2(acc[i][j][2], acc[i][j][3]);
            }
            __syncwarp();
            long r0 = tb + warp_m * 64 + i * 16;
            long c0 = ob0 + nb * 128 + warp_n * 32;
#pragma unroll
            for (int s = 0; s < 4; s++) {
                int q = lane + s * 32;
                int row = q >> 3, c4 = q & 7;
                float4 v = *reinterpret_cast<float4*>(&wb[row * WSTRIDE + c4 * 4]);
                __stcs(reinterpret_cast<float4*>(&out[(r0 + row) * OUTF + c0 + c4 * 4]), v);
            }
            __syncwarp();
        }
    }
}

// ---------------------------------------------------------------------------
extern "C" void kernel_launch(void* const* d_in, const int* in_sizes, int n_in,
                              void* d_out, int out_size) {
    const float* x     = (const float*)d_in[0];  // [16384,1024]
    const float* basis = (const float*)d_in[1];  // [32,1024]
    const float* phase = (const float*)d_in[2];  // [4096,32]
    const float* amp   = (const float*)d_in[3];  // [4096,32]
    float* out = (float*)d_out;                  // [16384,4096]

    cudaFuncSetAttribute(holo_tf32_kernel,
                         cudaFuncAttributeMaxDynamicSharedMemorySize, SM3_TOTAL);

    resonance_tf32_kernel<<<512 + 32, 128>>>(x, basis, phase, amp);
    dim3 gridC(OUTF / 256, TOKENS / 128);
    holo_tf32_kernel<<<gridC, 256, SM3_TOTAL>>>(out);
}

// round 16
// speedup vs baseline: 1.4063x; 1.0246x over previous
#include <cuda_runtime.h>
#include <cuda_bf16.h>
#include <cstdint>

// out[t][o] = sum_h R[t][h] * W[o][h],  R = x @ basis^T, W = amp*cos(phase)
// SINGLE fused launch with flag-based producer/consumer overlap:
//   bids [0,128):    resonance producers (128 tokens/CTA, TF32 mma)
//   bids [128,144):  W prep
//   bids [144,2192): holo consumers (R9-proven body), spin on flags
#define TOKENS 16384
#define INF    1024
#define HARM   32
#define OUTF   4096

__device__ __align__(16) float g_R[TOKENS * HARM];   // 2 MB
__device__ __align__(16) float g_W[OUTF * HARM];     // 512 KB
__device__ int g_flags[144];   // [0,128): R block flags; [128,144): W flags

__device__ __forceinline__ uint32_t smem_u32(const void* p) {
    uint32_t a;
    asm("{ .reg .u64 t; cvta.to.shared.u64 t, %1; cvt.u32.u64 %0, t; }"
        : "=r"(a) : "l"(p));
    return a;
}
__device__ __forceinline__ float tf32_rna(float v) {
    float r;
    asm("cvt.rna.tf32.f32 %0, %1;" : "=f"(r) : "f"(v));
    return r;
}
__device__ __forceinline__ uint32_t tf32_r(uint32_t v) {
    uint32_t r;
    asm("cvt.rna.tf32.f32 %0, %1;" : "=r"(r) : "r"(v));
    return r;
}

#define XPITCH 68
#define TPITCH 36
#define TILE_BYTES (128 * TPITCH * 4)       // 18432
#define SMF_TOTAL (3 * TILE_BYTES)          // 55296 dynamic (holo); res uses 43520
#define WSTRIDE 40
#define NBT 2
#define NB_RES 128
#define NB_W   16
#define NB_PROD (NB_RES + NB_W)             // 144

__global__ __launch_bounds__(256, 2) void holo_fused_kernel(
    const float* __restrict__ x, const float* __restrict__ basis,
    const float* __restrict__ phase, const float* __restrict__ amp,
    float* __restrict__ out) {
    extern __shared__ char smem[];
    __shared__ float wstage[8][16 * WSTRIDE];

    int bid  = blockIdx.x;
    int tid  = threadIdx.x;
    int lane = tid & 31;
    int wid  = tid >> 5;

    // ======================= W-prep producers =======================
    if (bid >= NB_RES && bid < NB_PROD) {
        int idx = bid - NB_RES;
        int base = idx * 8192;
#pragma unroll
        for (int r = 0; r < 32; r++) {
            int q = base + tid + r * 256;
            g_W[q] = tf32_rna(amp[q] * cosf(phase[q]));
        }
        __syncthreads();
        if (tid == 0) { __threadfence(); atomicExch(&g_flags[NB_RES + idx], 1); }
        return;
    }

    // ======================= Resonance producers =======================
    if (bid < NB_RES) {
        float* sx = reinterpret_cast<float*>(smem);               // 128 x 68
        float* sb = reinterpret_cast<float*>(smem + 128 * XPITCH * 4);  // 32 x 68
        uint32_t sx_b = smem_u32(sx), sb_b = smem_u32(sb);

        int tb = bid * 128;
        int warp_m = wid;   // 0..7, 16 rows each

        float acc[4][4];
#pragma unroll
        for (int j = 0; j < 4; j++)
#pragma unroll
            for (int c = 0; c < 4; c++) acc[j][c] = 0.0f;

        const float4* gx = reinterpret_cast<const float4*>(x);
        const float4* gb = reinterpret_cast<const float4*>(basis);

        float4 xp[8], bp[2];
#pragma unroll
        for (int r = 0; r < 8; r++) {
            int q = tid + r * 256;            // 0..2047
            int row = q >> 4, c4 = q & 15;
            xp[r] = gx[(long)(tb + row) * (INF / 4) + c4];
        }
#pragma unroll
        for (int r = 0; r < 2; r++) {
            int q = tid + r * 256;            // 0..511
            int row = q >> 4, c4 = q & 15;
            bp[r] = gb[row * (INF / 4) + c4];
        }

        for (int ck = 0; ck < 16; ck++) {
            if (ck > 0) __syncthreads();
#pragma unroll
            for (int r = 0; r < 8; r++) {
                int q = tid + r * 256;
                int row = q >> 4, c4 = q & 15;
                *reinterpret_cast<float4*>(&sx[row * XPITCH + c4 * 4]) = xp[r];
            }
#pragma unroll
            for (int r = 0; r < 2; r++) {
                int q = tid + r * 256;
                int row = q >> 4, c4 = q & 15;
                *reinterpret_cast<float4*>(&sb[row * XPITCH + c4 * 4]) = bp[r];
            }
            __syncthreads();

            if (ck < 15) {
                int kc4 = (ck + 1) * 16;
#pragma unroll
                for (int r = 0; r < 8; r++) {
                    int q = tid + r * 256;
                    int row = q >> 4, c4 = q & 15;
                    xp[r] = gx[(long)(tb + row) * (INF / 4) + kc4 + c4];
                }
#pragma unroll
                for (int r = 0; r < 2; r++) {
                    int q = tid + r * 256;
                    int row = q >> 4, c4 = q & 15;
                    bp[r] = gb[row * (INF / 4) + kc4 + c4];
                }
            }

#pragma unroll
            for (int ks = 0; ks < 8; ks++) {
                uint32_t af[4];
                {
                    int row = warp_m * 16 + (lane & 15);
                    uint32_t ao = sx_b + (uint32_t)row * (XPITCH * 4) + ks * 32 + (lane >> 4) * 16;
                    asm volatile(
                        "ldmatrix.sync.aligned.m8n8.x4.shared.b16 {%0,%1,%2,%3}, [%4];"
                        : "=r"(af[0]), "=r"(af[1]), "=r"(af[2]), "=r"(af[3])
                        : "r"(ao));
#pragma unroll
                    for (int c = 0; c < 4; c++) af[c] = tf32_r(af[c]);
                }
#pragma unroll
                for (int j = 0; j < 4; j++) {
                    int nrow = j * 8 + (lane & 7);
                    uint32_t bo = sb_b + (uint32_t)nrow * (XPITCH * 4) + ks * 32 + ((lane >> 3) & 1) * 16;
                    uint32_t bf[2];
                    asm volatile(
                        "ldmatrix.sync.aligned.m8n8.x2.shared.b16 {%0,%1}, [%2];"
                        : "=r"(bf[0]), "=r"(bf[1]) : "r"(bo));
                    bf[0] = tf32_r(bf[0]);
                    bf[1] = tf32_r(bf[1]);
                    asm volatile(
                        "mma.sync.aligned.m16n8k8.row.col.f32.tf32.tf32.f32 "
                        "{%0,%1,%2,%3}, {%4,%5,%6,%7}, {%8,%9}, {%0,%1,%2,%3};"
                        : "+f"(acc[j][0]), "+f"(acc[j][1]), "+f"(acc[j][2]), "+f"(acc[j][3])
                        : "r"(af[0]), "r"(af[1]), "r"(af[2]), "r"(af[3]),
                          "r"(bf[0]), "r"(bf[1]));
                }
            }
        }

        int qrow = lane >> 2;
        int qcol = (lane & 3) * 2;
#pragma unroll
        for (int j = 0; j < 4; j++) {
#pragma unroll
            for (int hh = 0; hh < 2; hh++) {
                long t = tb + warp_m * 16 + qrow + hh * 8;
                float v0 = tf32_rna(acc[j][hh * 2 + 0]);
                float v1 = tf32_rna(acc[j][hh * 2 + 1]);
                *reinterpret_cast<float2*>(&g_R[t * HARM + j * 8 + qcol]) =
                    make_float2(v0, v1);
            }
        }
        __syncthreads();
        if (tid == 0) { __threadfence(); atomicExch(&g_flags[bid], 1); }
        return;
    }

    // ======================= Holo consumers =======================
    int hb = bid - NB_PROD;
    int tb_idx = hb >> 4;                // 0..127 (tb-major: matches producer order)
    int ob0 = (hb & 15) * 256;
    int tb = tb_idx * 128;

    // Spin until our R block and W slice are published.
    if (tid == 0) {
        while (atomicAdd(&g_flags[tb_idx], 0) == 0) __nanosleep(128);
        while (atomicAdd(&g_flags[NB_RES + (ob0 >> 8)], 0) == 0) __nanosleep(128);
        __threadfence();
    }
    __syncthreads();

    char* sA = smem;
    int warp_m = wid >> 2;   // 0..1
    int warp_n = wid & 3;    // 0..3

    const float4* gA = reinterpret_cast<const float4*>(&g_R[(long)tb * HARM]);
    const float4* gB = reinterpret_cast<const float4*>(&g_W[(long)ob0 * HARM]);

#pragma unroll
    for (int r = 0; r < 4; r++) {
        int q = tid + r * 256;        // 0..1023
        int row = q >> 3, ch = q & 7;
        uint32_t soff = (uint32_t)row * (TPITCH * 4) + ch * 16;
        *reinterpret_cast<float4*>(sA + soff) = gA[q];
        *reinterpret_cast<float4*>(sA + TILE_BYTES + soff) = gB[q];
        *reinterpret_cast<float4*>(sA + 2 * TILE_BYTES + soff) = gB[1024 + q];
    }
    __syncthreads();

    uint32_t sAb = smem_u32(sA);
    int qrow = lane >> 2;
    int qcol = (lane & 3) * 2;

#pragma unroll
    for (int nb = 0; nb < NBT; nb++) {
        uint32_t sBb = sAb + TILE_BYTES + (uint32_t)nb * TILE_BYTES;

        float acc[4][4][4];
#pragma unroll
        for (int i = 0; i < 4; i++)
#pragma unroll
            for (int j = 0; j < 4; j++)
#pragma unroll
                for (int c = 0; c < 4; c++) acc[i][j][c] = 0.0f;

#pragma unroll
        for (int ks = 0; ks < 4; ks++) {
            uint32_t af[4][4];
#pragma unroll
            for (int i = 0; i < 4; i++) {
                int row = warp_m * 64 + i * 16 + (lane & 15);
                uint32_t addr = sAb + (uint32_t)row * (TPITCH * 4) + ks * 32 + (lane >> 4) * 16;
                asm volatile(
                    "ldmatrix.sync.aligned.m8n8.x4.shared.b16 {%0,%1,%2,%3}, [%4];"
                    : "=r"(af[i][0]), "=r"(af[i][1]), "=r"(af[i][2]), "=r"(af[i][3])
                    : "r"(addr));
            }
            uint32_t bf[4][2];
#pragma unroll
            for (int j = 0; j < 4; j++) {
                int orow = warp_n * 32 + j * 8 + (lane & 7);
                uint32_t addr = sBb + (uint32_t)orow * (TPITCH * 4) + ks * 32 + ((lane >> 3) & 1) * 16;
                asm volatile(
                    "ldmatrix.sync.aligned.m8n8.x2.shared.b16 {%0,%1}, [%2];"
                    : "=r"(bf[j][0]), "=r"(bf[j][1])
                    : "r"(addr));
            }
#pragma unroll
            for (int i = 0; i < 4; i++)
#pragma unroll
                for (int j = 0; j < 4; j++) {
                    asm volatile(
                        "mma.sync.aligned.m16n8k8.row.col.f32.tf32.tf32.f32 "
                        "{%0,%1,%2,%3}, {%4,%5,%6,%7}, {%8,%9}, {%0,%1,%2,%3};"
                        : "+f"(acc[i][j][0]), "+f"(acc[i][j][1]),
                          "+f"(acc[i][j][2]), "+f"(acc[i][j][3])
                        : "r"(af[i][0]), "r"(af[i][1]), "r"(af[i][2]), "r"(af[i][3]),
                          "r"(bf[j][0]), "r"(bf[j][1]));
                }
        }

        float* wb = wstage[wid];
#pragma unroll
        for (int i = 0; i < 4; i++) {
#pragma unroll
            for (int j = 0; j < 4; j++) {
                *reinterpret_cast<float2*>(&wb[qrow * WSTRIDE + j * 8 + qcol]) =
                    make_float2(acc[i][j][0], acc[i][j][1]);
                *reinterpret_cast<float2*>(&wb[(qrow + 8) * WSTRIDE + j * 8 + qcol]) =
                    make_float2(acc[i][j][2], acc[i][j][3]);
            }
            __syncwarp();
            long r0 = tb + warp_m * 64 + i * 16;
            long c0 = ob0 + nb * 128 + warp_n * 32;
#pragma unroll
            for (int s = 0; s < 4; s++) {
                int q = lane + s * 32;
                int row = q >> 3, c4 = q & 7;
                float4 v = *reinterpret_cast<float4*>(&wb[row * WSTRIDE + c4 * 4]);
                __stcs(reinterpret_cast<float4*>(&out[(r0 + row) * OUTF + c0 + c4 * 4]), v);
            }
            __syncwarp();
        }
    }
}

// ---------------------------------------------------------------------------
extern "C" void kernel_launch(void* const* d_in, const int* in_sizes, int n_in,
                              void* d_out, int out_size) {
    const float* x     = (const float*)d_in[0];  // [16384,1024]
    const float* basis = (const float*)d_in[1];  // [32,1024]
    const float* phase = (const float*)d_in[2];  // [4096,32]
    const float* amp   = (const float*)d_in[3];  // [4096,32]
    float* out = (float*)d_out;                  // [16384,4096]

    cudaFuncSetAttribute(holo_fused_kernel,
                         cudaFuncAttributeMaxDynamicSharedMemorySize, SMF_TOTAL);

    // Reset flags each launch (graph-capturable, deterministic).
    void* fp = nullptr;
    cudaGetSymbolAddress(&fp, g_flags);
    cudaMemsetAsync(fp, 0, sizeof(int) * NB_PROD);

    holo_fused_kernel<<<NB_PROD + 2048, 256, SMF_TOTAL>>>(x, basis, phase, amp, out);
}

// round 17
// speedup vs baseline: 1.4412x; 1.0248x over previous
#include <cuda_runtime.h>
#include <cuda_bf16.h>
#include <cstdint>

// out[t][o] = sum_h R[t][h] * W[o][h],  R = x @ basis^T, W = amp*cos(phase)
// Step 2 (R): split-K TF32 mma — 2 partials over K=512 each (2x CTAs -> full
//             chip), summed + tf32-rounded during holo's A-tile fill.
// Step 3 (out): mma.m16n8k8 TF32, R9-proven staged epilogue.
#define TOKENS 16384
#define INF    1024
#define HARM   32
#define OUTF   4096

__device__ __align__(16) float g_Rp[2][TOKENS * HARM];  // 4 MB (2 partials)
__device__ __align__(16) float g_W[OUTF * HARM];        // 512 KB

__device__ __forceinline__ uint32_t smem_u32(const void* p) {
    uint32_t a;
    asm("{ .reg .u64 t; cvta.to.shared.u64 t, %1; cvt.u32.u64 %0, t; }"
        : "=r"(a) : "l"(p));
    return a;
}
__device__ __forceinline__ float tf32_rna(float v) {
    float r;
    asm("cvt.rna.tf32.f32 %0, %1;" : "=f"(r) : "f"(v));
    return r;
}
__device__ __forceinline__ uint32_t tf32_r(uint32_t v) {
    uint32_t r;
    asm("cvt.rna.tf32.f32 %0, %1;" : "=r"(r) : "r"(v));
    return r;
}

// ---------------------------------------------------------------------------
// Step 2 (+W prep): CTAs [0,512): partial R over K=512 (part = bid>>8,
// 64-token tile, R9 mainloop with 8 chunks). CTAs [512,544): W prep.
// ---------------------------------------------------------------------------
#define XPITCH 68
__global__ __launch_bounds__(128) void resonance_splitk_kernel(
    const float* __restrict__ x, const float* __restrict__ basis,
    const float* __restrict__ phase, const float* __restrict__ amp) {
    if (blockIdx.x >= 512) {
        int base = (blockIdx.x - 512) * 4096;
#pragma unroll
        for (int r = 0; r < 32; r++) {
            int idx = base + threadIdx.x + r * 128;
            g_W[idx] = tf32_rna(amp[idx] * cosf(phase[idx]));
        }
        return;
    }

    __shared__ float sx[64 * XPITCH];
    __shared__ float sb[32 * XPITCH];

    int tid  = threadIdx.x;
    int lane = tid & 31;
    int wid  = tid >> 5;
    int part = blockIdx.x >> 8;                 // 0..1
    int tb   = (blockIdx.x & 255) * 64;
    int k0f4 = part * 128;                      // K offset in float4 units

    uint32_t sx_b = smem_u32(sx), sb_b = smem_u32(sb);

    float acc[4][4];
#pragma unroll
    for (int j = 0; j < 4; j++)
#pragma unroll
        for (int c = 0; c < 4; c++) acc[j][c] = 0.0f;

    const float4* gx = reinterpret_cast<const float4*>(x);
    const float4* gb = reinterpret_cast<const float4*>(basis);

    float4 xp[8], bp[4];
#pragma unroll
    for (int r = 0; r < 8; r++) {
        int q = tid + r * 128;
        int row = q >> 4, c4 = q & 15;
        xp[r] = gx[(long)(tb + row) * (INF / 4) + k0f4 + c4];
    }
#pragma unroll
    for (int r = 0; r < 4; r++) {
        int q = tid + r * 128;
        int row = q >> 4, c4 = q & 15;
        bp[r] = gb[row * (INF / 4) + k0f4 + c4];
    }

    for (int ck = 0; ck < 8; ck++) {
        if (ck > 0) __syncthreads();
#pragma unroll
        for (int r = 0; r < 8; r++) {
            int q = tid + r * 128;
            int row = q >> 4, c4 = q & 15;
            *reinterpret_cast<float4*>(&sx[row * XPITCH + c4 * 4]) = xp[r];
        }
#pragma unroll
        for (int r = 0; r < 4; r++) {
            int q = tid + r * 128;
            int row = q >> 4, c4 = q & 15;
            *reinterpret_cast<float4*>(&sb[row * XPITCH + c4 * 4]) = bp[r];
        }
        __syncthreads();

        if (ck < 7) {
            int kc4 = k0f4 + (ck + 1) * 16;
#pragma unroll
            for (int r = 0; r < 8; r++) {
                int q = tid + r * 128;
                int row = q >> 4, c4 = q & 15;
                xp[r] = gx[(long)(tb + row) * (INF / 4) + kc4 + c4];
            }
#pragma unroll
            for (int r = 0; r < 4; r++) {
                int q = tid + r * 128;
                int row = q >> 4, c4 = q & 15;
                bp[r] = gb[row * (INF / 4) + kc4 + c4];
            }
        }

#pragma unroll
        for (int ks = 0; ks < 8; ks++) {
            uint32_t af[4];
            {
                int row = wid * 16 + (lane & 15);
                uint32_t ao = sx_b + (uint32_t)row * (XPITCH * 4) + ks * 32 + (lane >> 4) * 16;
                asm volatile(
                    "ldmatrix.sync.aligned.m8n8.x4.shared.b16 {%0,%1,%2,%3}, [%4];"
                    : "=r"(af[0]), "=r"(af[1]), "=r"(af[2]), "=r"(af[3])
                    : "r"(ao));
#pragma unroll
                for (int c = 0; c < 4; c++) af[c] = tf32_r(af[c]);
            }
#pragma unroll
            for (int j = 0; j < 4; j++) {
                int nrow = j * 8 + (lane & 7);
                uint32_t bo = sb_b + (uint32_t)nrow * (XPITCH * 4) + ks * 32 + ((lane >> 3) & 1) * 16;
                uint32_t bf[2];
                asm volatile(
                    "ldmatrix.sync.aligned.m8n8.x2.shared.b16 {%0,%1}, [%2];"
                    : "=r"(bf[0]), "=r"(bf[1]) : "r"(bo));
                bf[0] = tf32_r(bf[0]);
                bf[1] = tf32_r(bf[1]);
                asm volatile(
                    "mma.sync.aligned.m16n8k8.row.col.f32.tf32.tf32.f32 "
                    "{%0,%1,%2,%3}, {%4,%5,%6,%7}, {%8,%9}, {%0,%1,%2,%3};"
                    : "+f"(acc[j][0]), "+f"(acc[j][1]), "+f"(acc[j][2]), "+f"(acc[j][3])
                    : "r"(af[0]), "r"(af[1]), "r"(af[2]), "r"(af[3]),
                      "r"(bf[0]), "r"(bf[1]));
            }
        }
    }

    // Epilogue: raw fp32 partials (rounded after the split-K sum, in holo).
    int qrow = lane >> 2;
    int qcol = (lane & 3) * 2;
    float* gR = g_Rp[part];
#pragma unroll
    for (int j = 0; j < 4; j++) {
#pragma unroll
        for (int hh = 0; hh < 2; hh++) {
            long t = tb + wid * 16 + qrow + hh * 8;
            *reinterpret_cast<float2*>(&gR[t * HARM + j * 8 + qcol]) =
                make_float2(acc[j][hh * 2 + 0], acc[j][hh * 2 + 1]);
        }
    }
}

// ---------------------------------------------------------------------------
// Step 3: out = R @ W^T via mma.m16n8k8 TF32, K=32 single term.
// CTA 128 tokens x 256 outputs (2 B-subtiles up-front). 8 warps 2(m)x4(n).
// A-fill sums the 2 split-K partials and tf32-rounds. Staged epilogue.
// ---------------------------------------------------------------------------
#define TPITCH 36
#define TILE_BYTES (128 * TPITCH * 4)       // 18432
#define SM3_TOTAL (3 * TILE_BYTES)          // 55296
#define WSTRIDE 40
#define NBT 2

__global__ __launch_bounds__(256, 2) void holo_tf32_kernel(float* __restrict__ out) {
    extern __shared__ char smem[];
    __shared__ float wstage[8][16 * WSTRIDE];
    char* sA = smem;

    int tid  = threadIdx.x;
    int lane = tid & 31;
    int wid  = tid >> 5;
    int warp_m = wid >> 2;   // 0..1
    int warp_n = wid & 3;    // 0..3

    int ob0 = blockIdx.x * 256;
    int tb  = blockIdx.y * 128;

    const float4* gA0 = reinterpret_cast<const float4*>(&g_Rp[0][(long)tb * HARM]);
    const float4* gA1 = reinterpret_cast<const float4*>(&g_Rp[1][(long)tb * HARM]);
    const float4* gB  = reinterpret_cast<const float4*>(&g_W[(long)ob0 * HARM]);

#pragma unroll
    for (int r = 0; r < 4; r++) {
        int q = tid + r * 256;        // 0..1023
        int row = q >> 3, ch = q & 7;
        uint32_t soff = (uint32_t)row * (TPITCH * 4) + ch * 16;
        float4 a0 = gA0[q], a1 = gA1[q];
        float4 s;
        s.x = tf32_rna(a0.x + a1.x);
        s.y = tf32_rna(a0.y + a1.y);
        s.z = tf32_rna(a0.z + a1.z);
        s.w = tf32_rna(a0.w + a1.w);
        *reinterpret_cast<float4*>(sA + soff) = s;
        *reinterpret_cast<float4*>(sA + TILE_BYTES + soff) = gB[q];
        *reinterpret_cast<float4*>(sA + 2 * TILE_BYTES + soff) = gB[1024 + q];
    }
    __syncthreads();

    uint32_t sAb = smem_u32(sA);
    int qrow = lane >> 2;
    int qcol = (lane & 3) * 2;

#pragma unroll
    for (int nb = 0; nb < NBT; nb++) {
        uint32_t sBb = sAb + TILE_BYTES + (uint32_t)nb * TILE_BYTES;

        float acc[4][4][4];
#pragma unroll
        for (int i = 0; i < 4; i++)
#pragma unroll
            for (int j = 0; j < 4; j++)
#pragma unroll
                for (int c = 0; c < 4; c++) acc[i][j][c] = 0.0f;

#pragma unroll
        for (int ks = 0; ks < 4; ks++) {
            uint32_t af[4][4];
#pragma unroll
            for (int i = 0; i < 4; i++) {
                int row = warp_m * 64 + i * 16 + (lane & 15);
                uint32_t addr = sAb + (uint32_t)row * (TPITCH * 4) + ks * 32 + (lane >> 4) * 16;
                asm volatile(
                    "ldmatrix.sync.aligned.m8n8.x4.shared.b16 {%0,%1,%2,%3}, [%4];"
                    : "=r"(af[i][0]), "=r"(af[i][1]), "=r"(af[i][2]), "=r"(af[i][3])
                    : "r"(addr));
            }
            uint32_t bf[4][2];
#pragma unroll
            for (int j = 0; j < 4; j++) {
                int orow = warp_n * 32 + j * 8 + (lane & 7);
                uint32_t addr = sBb + (uint32_t)orow * (TPITCH * 4) + ks * 32 + ((lane >> 3) & 1) * 16;
                asm volatile(
                    "ldmatrix.sync.aligned.m8n8.x2.shared.b16 {%0,%1}, [%2];"
                    : "=r"(bf[j][0]), "=r"(bf[j][1])
                    : "r"(addr));
            }
#pragma unroll
            for (int i = 0; i < 4; i++)
#pragma unroll
                for (int j = 0; j < 4; j++) {
                    asm volatile(
                        "mma.sync.aligned.m16n8k8.row.col.f32.tf32.tf32.f32 "
                        "{%0,%1,%2,%3}, {%4,%5,%6,%7}, {%8,%9}, {%0,%1,%2,%3};"
                        : "+f"(acc[i][j][0]), "+f"(acc[i][j][1]),
                          "+f"(acc[i][j][2]), "+f"(acc[i][j][3])
                        : "r"(af[i][0]), "r"(af[i][1]), "r"(af[i][2]), "r"(af[i][3]),
                          "r"(bf[j][0]), "r"(bf[j][1]));
                }
        }

        float* wb = wstage[wid];
#pragma unroll
        for (int i = 0; i < 4; i++) {
#pragma unroll
            for (int j = 0; j < 4; j++) {
                *reinterpret_cast<float2*>(&wb[qrow * WSTRIDE + j * 8 + qcol]) =
                    make_float2(acc[i][j][0], acc[i][j][1]);
                *reinterpret_cast<float2*>(&wb[(qrow + 8) * WSTRIDE + j * 8 + qcol]) =
                    make_float2(acc[i][j][2], acc[i][j][3]);
            }
            __syncwarp();
            long r0 = tb + warp_m * 64 + i * 16;
            long c0 = ob0 + nb * 128 + warp_n * 32;
#pragma unroll
            for (int s = 0; s < 4; s++) {
                int q = lane + s * 32;
                int row = q >> 3, c4 = q & 7;
                float4 v = *reinterpret_cast<float4*>(&wb[row * WSTRIDE + c4 * 4]);
                __stcs(reinterpret_cast<float4*>(&out[(r0 + row) * OUTF + c0 + c4 * 4]), v);
            }
            __syncwarp();
        }
    }
}

// ---------------------------------------------------------------------------
extern "C" void kernel_launch(void* const* d_in, const int* in_sizes, int n_in,
                              void* d_out, int out_size) {
    const float* x     = (const float*)d_in[0];  // [16384,1024]
    const float* basis = (const float*)d_in[1];  // [32,1024]
    const float* phase = (const float*)d_in[2];  // [4096,32]
    const float* amp   = (const float*)d_in[3];  // [4096,32]
    float* out = (float*)d_out;                  // [16384,4096]

    cudaFuncSetAttribute(holo_tf32_kernel,
                         cudaFuncAttributeMaxDynamicSharedMemorySize, SM3_TOTAL);

    resonance_splitk_kernel<<<512 + 32, 128>>>(x, basis, phase, amp);
    dim3 gridC(OUTF / 256, TOKENS / 128);
    holo_tf32_kernel<<<gridC, 256, SM3_TOTAL>>>(out);
}